// round 8
// baseline (speedup 1.0000x reference)
#include <cuda_runtime.h>
#include <cuda_fp16.h>
#include <cstdint>
#include <math_constants.h>

// ---------------------------------------------------------------------------
// RWKV TimeMix: T=4096, C=2048
//   fp16 mma.sync GEMMs, 128x64 CTA tiles (wave-packed), occ 3,
//   conflict-free pitch-20 smem, cp.async 4-stage pipeline
//   + chunk-parallel WKV scan (128 chunks).
// ---------------------------------------------------------------------------

#define TT 4096
#define CC 2048
#define NCHUNK 128
#define CHUNK (TT / NCHUNK)   // 32

// Scratch (device globals: no allocation allowed anywhere)
__device__ __half g_xk[TT * CC];
__device__ __half g_xv[TT * CC];
__device__ __half g_xr[TT * CC];
__device__ __half g_y [TT * CC];          // gated output (Wo GEMM A operand)
__device__ float  g_k [TT * CC];
__device__ float  g_v [TT * CC];
__device__ float  g_r [TT * CC];
__device__ float  g_lp[NCHUNK * CC];
__device__ float  g_lq[NCHUNK * CC];
__device__ float  g_lo[NCHUNK * CC];
__device__ float  g_cp[NCHUNK * CC];
__device__ float  g_cq[NCHUNK * CC];
__device__ float  g_co[NCHUNK * CC];
// K-major (transposed) weights, fp16
__device__ __half g_WkT[CC * CC];
__device__ __half g_WvT[CC * CC];
__device__ __half g_WrT[CC * CC];
__device__ __half g_WoT[CC * CC];

// ---------------------------------------------------------------------------
// Helpers
// ---------------------------------------------------------------------------
__device__ __forceinline__ uint32_t smem_u32(const void* p) {
    uint32_t a;
    asm("{ .reg .u64 t; cvta.to.shared.u64 t, %1; cvt.u32.u64 %0, t; }"
        : "=r"(a) : "l"(p));
    return a;
}

__device__ __forceinline__ unsigned h2u(__half2 h) {
    return *reinterpret_cast<unsigned*>(&h);
}

// ---------------------------------------------------------------------------
// Elementwise mix -> fp16 operands
// ---------------------------------------------------------------------------
__global__ __launch_bounds__(256) void mix_kernel(
    const float* __restrict__ x,
    const float* __restrict__ tmk,
    const float* __restrict__ tmv,
    const float* __restrict__ tmr)
{
    int i4 = blockIdx.x * 256 + threadIdx.x;      // float4 index over T*C/4
    int c4 = i4 & (CC / 4 - 1);

    float4 xc = ((const float4*)x)[i4];
    float4 xp;
    if (i4 >= CC / 4) xp = ((const float4*)x)[i4 - CC / 4];
    else              xp = make_float4(0.f, 0.f, 0.f, 0.f);

    float4 mk = ((const float4*)tmk)[c4];
    float4 mv = ((const float4*)tmv)[c4];
    float4 mr = ((const float4*)tmr)[c4];

    __half2 k01 = __floats2half2_rn(xp.x + mk.x * (xc.x - xp.x), xp.y + mk.y * (xc.y - xp.y));
    __half2 k23 = __floats2half2_rn(xp.z + mk.z * (xc.z - xp.z), xp.w + mk.w * (xc.w - xp.w));
    __half2 v01 = __floats2half2_rn(xp.x + mv.x * (xc.x - xp.x), xp.y + mv.y * (xc.y - xp.y));
    __half2 v23 = __floats2half2_rn(xp.z + mv.z * (xc.z - xp.z), xp.w + mv.w * (xc.w - xp.w));
    __half2 r01 = __floats2half2_rn(xp.x + mr.x * (xc.x - xp.x), xp.y + mr.y * (xc.y - xp.y));
    __half2 r23 = __floats2half2_rn(xp.z + mr.z * (xc.z - xp.z), xp.w + mr.w * (xc.w - xp.w));

    ((uint2*)g_xk)[i4] = make_uint2(h2u(k01), h2u(k23));
    ((uint2*)g_xv)[i4] = make_uint2(h2u(v01), h2u(v23));
    ((uint2*)g_xr)[i4] = make_uint2(h2u(r01), h2u(r23));
}

// ---------------------------------------------------------------------------
// Fused weight transpose -> fp16:  WT[n][k] = half(W[k][n]); z selects matrix
// ---------------------------------------------------------------------------
__global__ __launch_bounds__(256) void transpose_half4(
    const float* __restrict__ W0, const float* __restrict__ W1,
    const float* __restrict__ W2, const float* __restrict__ W3)
{
    __shared__ float t[32][33];
    const float* W;
    __half* WT;
    switch (blockIdx.z) {
        case 0:  W = W0; WT = g_WkT; break;
        case 1:  W = W1; WT = g_WvT; break;
        case 2:  W = W2; WT = g_WrT; break;
        default: W = W3; WT = g_WoT; break;
    }
    int bx = blockIdx.x * 32, by = blockIdx.y * 32;
    int tx = threadIdx.x, ty = threadIdx.y;
#pragma unroll
    for (int j = 0; j < 32; j += 8)
        t[ty + j][tx] = W[(size_t)(by + ty + j) * CC + bx + tx];
    __syncthreads();
#pragma unroll
    for (int j = 0; j < 32; j += 8)
        WT[(size_t)(bx + ty + j) * CC + by + tx] = __float2half(t[tx][ty + j]);
}

// ---------------------------------------------------------------------------
// FP16 GEMM: D[M,N] = A[M,K] @ Bt[N,K]^T  (both k-contiguous, half)
// Block 128x64, BK=32, 128 threads (4 warps stacked in M, warp tile 32x64),
// 4-stage cp.async pipeline, pitch-20-word conflict-free smem, occ 3.
// ---------------------------------------------------------------------------
#define BM 128
#define BN 64
#define BK 32
#define PITCHW 20                    // 32-bit words per row (32 halves + 8 pad)
#define AST_W (BM * PITCHW)          // 2560 words: A tile
#define BST_W (BN * PITCHW)          // 1280 words: B tile
#define STAGE_B ((AST_W + BST_W) * 4)   // 15360 bytes
#define NSTAGE 4
#define SMEM_BYTES (NSTAGE * STAGE_B)   // 61440
#define NKT (CC / BK)                // 64

__device__ __forceinline__ void mma_f16(float* d, const unsigned* a, const unsigned* b) {
    asm volatile(
        "mma.sync.aligned.m16n8k16.row.col.f32.f16.f16.f32 "
        "{%0,%1,%2,%3}, {%4,%5,%6,%7}, {%8,%9}, {%0,%1,%2,%3};\n"
        : "+f"(d[0]), "+f"(d[1]), "+f"(d[2]), "+f"(d[3])
        : "r"(a[0]), "r"(a[1]), "r"(a[2]), "r"(a[3]), "r"(b[0]), "r"(b[1]));
}

__device__ __forceinline__ void cp16(uint32_t saddr, const void* gaddr) {
    asm volatile("cp.async.cg.shared.global [%0], [%1], 16;\n"
                 :: "r"(saddr), "l"(gaddr));
}

__device__ __forceinline__ void gemm_body(
    const __half* __restrict__ A, const __half* __restrict__ Bt,
    float* __restrict__ D, char* smem)
{
    const uint32_t sbase = smem_u32(smem);
    const int tid = threadIdx.x;
    const int wid = tid >> 5;
    const int lane = tid & 31;
    const int gp = lane >> 2;        // 0..7
    const int tg = lane & 3;         // 0..3
    const int wm = wid << 5;         // 0,32,64,96

    const int bm = blockIdx.y * BM;
    const int bn = blockIdx.x * BN;

    // loader mapping: row lr (+32j), 16B chunk lc (8 halves)
    const int lr = tid >> 2;         // 0..31
    const int lc = tid & 3;          // 0..3
    const __half* ga = A  + (size_t)(bm + lr) * CC + lc * 8;
    const __half* gb = Bt + (size_t)(bn + lr) * CC + lc * 8;
    const uint32_t swa = (uint32_t)(lr * PITCHW * 4 + lc * 16);

    float acc[2][8][4];
#pragma unroll
    for (int i = 0; i < 2; i++)
#pragma unroll
        for (int j = 0; j < 8; j++)
#pragma unroll
            for (int e = 0; e < 4; e++) acc[i][j][e] = 0.f;

#define LOAD_STAGE(ST, KT)                                                     \
    do {                                                                       \
        uint32_t _sa = sbase + (ST) * STAGE_B + swa;                           \
        uint32_t _sb = _sa + AST_W * 4;                                        \
        const __half* _ga = ga + (KT) * BK;                                    \
        const __half* _gb = gb + (KT) * BK;                                    \
        cp16(_sa,                    _ga);                                     \
        cp16(_sa + 32 * PITCHW * 4,  _ga + (size_t)32 * CC);                   \
        cp16(_sa + 64 * PITCHW * 4,  _ga + (size_t)64 * CC);                   \
        cp16(_sa + 96 * PITCHW * 4,  _ga + (size_t)96 * CC);                   \
        cp16(_sb,                    _gb);                                     \
        cp16(_sb + 32 * PITCHW * 4,  _gb + (size_t)32 * CC);                   \
        asm volatile("cp.async.commit_group;\n" ::: "memory");                 \
    } while (0)

    LOAD_STAGE(0, 0);
    LOAD_STAGE(1, 1);
    LOAD_STAGE(2, 2);

    const int abase0 = (wm + gp) * PITCHW + tg;
    const int bbase0 = gp * PITCHW + tg;

    for (int kt = 0; kt < NKT; kt++) {
        int ahead = NKT - 1 - kt;
        if (ahead >= 2)      asm volatile("cp.async.wait_group 2;\n" ::: "memory");
        else if (ahead == 1) asm volatile("cp.async.wait_group 1;\n" ::: "memory");
        else                 asm volatile("cp.async.wait_group 0;\n" ::: "memory");
        __syncthreads();

        if (kt + 3 < NKT) LOAD_STAGE((kt + 3) & 3, kt + 3);

        const unsigned* As = (const unsigned*)(smem + (kt & 3) * STAGE_B);
        const unsigned* Bs = As + AST_W;

#pragma unroll
        for (int ks = 0; ks < 2; ks++) {       // two k16 steps (word offset 8)
            const int ko = ks * 8;
            unsigned af[2][4];
            unsigned bf[8][2];
#pragma unroll
            for (int mi = 0; mi < 2; mi++) {
                int b = abase0 + mi * 16 * PITCHW + ko;
                af[mi][0] = As[b];                    // (m=gp,    k=2tg)
                af[mi][1] = As[b + 8 * PITCHW];       // (m=gp+8,  k=2tg)
                af[mi][2] = As[b + 4];                // (m=gp,    k=2tg+8)
                af[mi][3] = As[b + 8 * PITCHW + 4];   // (m=gp+8,  k=2tg+8)
            }
#pragma unroll
            for (int ni = 0; ni < 8; ni++) {
                int b = bbase0 + ni * 8 * PITCHW + ko;
                bf[ni][0] = Bs[b];                    // (n=gp, k=2tg)
                bf[ni][1] = Bs[b + 4];                // (n=gp, k=2tg+8)
            }
#pragma unroll
            for (int mi = 0; mi < 2; mi++)
#pragma unroll
                for (int ni = 0; ni < 8; ni++)
                    mma_f16(acc[mi][ni], af[mi], bf[ni]);
        }
    }

    // epilogue (fp32 out)
#pragma unroll
    for (int mi = 0; mi < 2; mi++) {
        int r0 = bm + wm + mi * 16 + gp;
#pragma unroll
        for (int ni = 0; ni < 8; ni++) {
            int c0 = bn + ni * 8 + tg * 2;
            *(float2*)&D[(size_t)r0 * CC + c0]       = make_float2(acc[mi][ni][0], acc[mi][ni][1]);
            *(float2*)&D[(size_t)(r0 + 8) * CC + c0] = make_float2(acc[mi][ni][2], acc[mi][ni][3]);
        }
    }
#undef LOAD_STAGE
}

// Fused k/v/r GEMMs: blockIdx.z selects operand triple (wave packing)
__global__ __launch_bounds__(128, 3) void gemm_fused3()
{
    extern __shared__ char smem[];
    const __half* A;
    const __half* B;
    float* D;
    if (blockIdx.z == 0)      { A = g_xk; B = g_WkT; D = g_k; }
    else if (blockIdx.z == 1) { A = g_xv; B = g_WvT; D = g_v; }
    else                      { A = g_xr; B = g_WrT; D = g_r; }
    gemm_body(A, B, D, smem);
}

__global__ __launch_bounds__(128, 3) void gemm_single(
    const __half* __restrict__ A, const __half* __restrict__ Bt, float* __restrict__ D)
{
    extern __shared__ char smem[];
    gemm_body(A, Bt, D, smem);
}

// ---------------------------------------------------------------------------
// WKV chunk-parallel scan (unchanged numerics, 128 chunks)
// ---------------------------------------------------------------------------
__global__ __launch_bounds__(256) void wkv_phaseA(const float* __restrict__ time_decay)
{
    int c = blockIdx.x * 256 + threadIdx.x;
    int ch = blockIdx.y;
    float w = -__expf(time_decay[c]);
    float p = 0.f, q = 0.f, o = -CUDART_INF_F;
    size_t idx = (size_t)(ch * CHUNK) * CC + c;
#pragma unroll 4
    for (int i = 0; i < CHUNK; i++, idx += CC) {
        float kt = g_k[idx];
        float vt = g_v[idx];
        float no = fmaxf(w + o, kt);
        float A2 = __expf(w + o - no);
        float B2 = __expf(kt - no);
        p = A2 * p + B2 * vt;
        q = A2 * q + B2;
        o = no;
    }
    g_lp[ch * CC + c] = p;
    g_lq[ch * CC + c] = q;
    g_lo[ch * CC + c] = o;
}

__global__ __launch_bounds__(256) void wkv_phaseB(const float* __restrict__ time_decay)
{
    int c = blockIdx.x * 256 + threadIdx.x;
    float w = -__expf(time_decay[c]);
    float d = w * (float)CHUNK;
    float p = 0.f, q = 0.f, o = -CUDART_INF_F;
    for (int ch = 0; ch < NCHUNK; ch++) {
        g_cp[ch * CC + c] = p;
        g_cq[ch * CC + c] = q;
        g_co[ch * CC + c] = o;
        float lp = g_lp[ch * CC + c];
        float lq = g_lq[ch * CC + c];
        float lo = g_lo[ch * CC + c];
        float o1 = o + d;
        float no = fmaxf(o1, lo);
        float e1 = __expf(o1 - no);
        float e2 = __expf(lo - no);
        p = e1 * p + e2 * lp;
        q = e1 * q + e2 * lq;
        o = no;
    }
}

// fuses sigmoid(r) gate; fp16 output (Wo GEMM A operand)
__global__ __launch_bounds__(256) void wkv_phaseC(
    const float* __restrict__ time_decay, const float* __restrict__ time_first)
{
    int c = blockIdx.x * 256 + threadIdx.x;
    int ch = blockIdx.y;
    float w = -__expf(time_decay[c]);
    float u = time_first[c];
    float p = g_cp[ch * CC + c];
    float q = g_cq[ch * CC + c];
    float o = g_co[ch * CC + c];
    size_t idx = (size_t)(ch * CHUNK) * CC + c;
#pragma unroll 4
    for (int i = 0; i < CHUNK; i++, idx += CC) {
        float kt = g_k[idx];
        float vt = g_v[idx];
        float rt = g_r[idx];
        float uk = u + kt;
        float no = fmaxf(o, uk);
        float Ae = __expf(o - no);
        float Be = __expf(uk - no);
        float y = __fdividef(Ae * p + Be * vt, Ae * q + Be);
        float sr = __fdividef(1.f, 1.f + __expf(-rt));
        g_y[idx] = __float2half(sr * y);
        float no2 = fmaxf(w + o, kt);
        float A2 = __expf(w + o - no2);
        float B2 = __expf(kt - no2);
        p = A2 * p + B2 * vt;
        q = A2 * q + B2;
        o = no2;
    }
}

// ---------------------------------------------------------------------------
// Launch
// ---------------------------------------------------------------------------
extern "C" void kernel_launch(void* const* d_in, const int* in_sizes, int n_in,
                              void* d_out, int out_size)
{
    (void)in_sizes; (void)n_in; (void)out_size;
    const float* x   = (const float*)d_in[0];
    const float* tfi = (const float*)d_in[1];
    const float* tmk = (const float*)d_in[2];
    const float* tmv = (const float*)d_in[3];
    const float* tmr = (const float*)d_in[4];
    const float* td  = (const float*)d_in[5];
    const float* Wk  = (const float*)d_in[6];
    const float* Wv  = (const float*)d_in[7];
    const float* Wr  = (const float*)d_in[8];
    const float* Wo  = (const float*)d_in[9];
    float* out = (float*)d_out;

    __half *p_y, *p_WoT;
    cudaGetSymbolAddress((void**)&p_y,  g_y);
    cudaGetSymbolAddress((void**)&p_WoT, g_WoT);

    cudaFuncSetAttribute(gemm_fused3, cudaFuncAttributeMaxDynamicSharedMemorySize, SMEM_BYTES);
    cudaFuncSetAttribute(gemm_single, cudaFuncAttributeMaxDynamicSharedMemorySize, SMEM_BYTES);

    const int elem4_blocks = (TT * CC / 4) / 256;  // 8192
    dim3 tgrid(CC / 32, CC / 32, 4), tblk(32, 8);
    transpose_half4<<<tgrid, tblk>>>(Wk, Wv, Wr, Wo);

    mix_kernel<<<elem4_blocks, 256>>>(x, tmk, tmv, tmr);

    dim3 g3(CC / BN, TT / BM, 3);   // (32, 32, 3) = 3072 CTAs
    gemm_fused3<<<g3, 128, SMEM_BYTES>>>();

    wkv_phaseA<<<dim3(CC / 256, NCHUNK), 256>>>(td);
    wkv_phaseB<<<CC / 256, 256>>>(td);
    wkv_phaseC<<<dim3(CC / 256, NCHUNK), 256>>>(td, tfi);

    dim3 g1(CC / BN, TT / BM);      // (32, 32) = 1024 CTAs
    gemm_single<<<g1, 128, SMEM_BYTES>>>(p_y, p_WoT, out);
}

// round 9
// speedup vs baseline: 1.0608x; 1.0608x over previous
#include <cuda_runtime.h>
#include <cuda_fp16.h>
#include <cstdint>
#include <math_constants.h>

// ---------------------------------------------------------------------------
// RWKV TimeMix: T=4096, C=2048
//   fp16 mma.sync GEMMs (R7 config: 128x128 tile, warp 64x64, occ 2,
//   conflict-free pitch-20 smem, cp.async 4-stage pipeline)
//   + chunk-parallel WKV scan (128 chunks, R8's improvement).
// ---------------------------------------------------------------------------

#define TT 4096
#define CC 2048
#define NCHUNK 128
#define CHUNK (TT / NCHUNK)   // 32

// Scratch (device globals: no allocation allowed anywhere)
__device__ __half g_xk[TT * CC];
__device__ __half g_xv[TT * CC];
__device__ __half g_xr[TT * CC];
__device__ __half g_y [TT * CC];          // gated output (Wo GEMM A operand)
__device__ float  g_k [TT * CC];
__device__ float  g_v [TT * CC];
__device__ float  g_r [TT * CC];
__device__ float  g_lp[NCHUNK * CC];
__device__ float  g_lq[NCHUNK * CC];
__device__ float  g_lo[NCHUNK * CC];
__device__ float  g_cp[NCHUNK * CC];
__device__ float  g_cq[NCHUNK * CC];
__device__ float  g_co[NCHUNK * CC];
// K-major (transposed) weights, fp16
__device__ __half g_WkT[CC * CC];
__device__ __half g_WvT[CC * CC];
__device__ __half g_WrT[CC * CC];
__device__ __half g_WoT[CC * CC];

// ---------------------------------------------------------------------------
// Helpers
// ---------------------------------------------------------------------------
__device__ __forceinline__ uint32_t smem_u32(const void* p) {
    uint32_t a;
    asm("{ .reg .u64 t; cvta.to.shared.u64 t, %1; cvt.u32.u64 %0, t; }"
        : "=r"(a) : "l"(p));
    return a;
}

__device__ __forceinline__ unsigned h2u(__half2 h) {
    return *reinterpret_cast<unsigned*>(&h);
}

// ---------------------------------------------------------------------------
// Elementwise mix -> fp16 operands
// ---------------------------------------------------------------------------
__global__ __launch_bounds__(256) void mix_kernel(
    const float* __restrict__ x,
    const float* __restrict__ tmk,
    const float* __restrict__ tmv,
    const float* __restrict__ tmr)
{
    int i4 = blockIdx.x * 256 + threadIdx.x;      // float4 index over T*C/4
    int c4 = i4 & (CC / 4 - 1);

    float4 xc = ((const float4*)x)[i4];
    float4 xp;
    if (i4 >= CC / 4) xp = ((const float4*)x)[i4 - CC / 4];
    else              xp = make_float4(0.f, 0.f, 0.f, 0.f);

    float4 mk = ((const float4*)tmk)[c4];
    float4 mv = ((const float4*)tmv)[c4];
    float4 mr = ((const float4*)tmr)[c4];

    __half2 k01 = __floats2half2_rn(xp.x + mk.x * (xc.x - xp.x), xp.y + mk.y * (xc.y - xp.y));
    __half2 k23 = __floats2half2_rn(xp.z + mk.z * (xc.z - xp.z), xp.w + mk.w * (xc.w - xp.w));
    __half2 v01 = __floats2half2_rn(xp.x + mv.x * (xc.x - xp.x), xp.y + mv.y * (xc.y - xp.y));
    __half2 v23 = __floats2half2_rn(xp.z + mv.z * (xc.z - xp.z), xp.w + mv.w * (xc.w - xp.w));
    __half2 r01 = __floats2half2_rn(xp.x + mr.x * (xc.x - xp.x), xp.y + mr.y * (xc.y - xp.y));
    __half2 r23 = __floats2half2_rn(xp.z + mr.z * (xc.z - xp.z), xp.w + mr.w * (xc.w - xp.w));

    ((uint2*)g_xk)[i4] = make_uint2(h2u(k01), h2u(k23));
    ((uint2*)g_xv)[i4] = make_uint2(h2u(v01), h2u(v23));
    ((uint2*)g_xr)[i4] = make_uint2(h2u(r01), h2u(r23));
}

// ---------------------------------------------------------------------------
// Fused weight transpose -> fp16:  WT[n][k] = half(W[k][n]); z selects matrix
// ---------------------------------------------------------------------------
__global__ __launch_bounds__(256) void transpose_half4(
    const float* __restrict__ W0, const float* __restrict__ W1,
    const float* __restrict__ W2, const float* __restrict__ W3)
{
    __shared__ float t[32][33];
    const float* W;
    __half* WT;
    switch (blockIdx.z) {
        case 0:  W = W0; WT = g_WkT; break;
        case 1:  W = W1; WT = g_WvT; break;
        case 2:  W = W2; WT = g_WrT; break;
        default: W = W3; WT = g_WoT; break;
    }
    int bx = blockIdx.x * 32, by = blockIdx.y * 32;
    int tx = threadIdx.x, ty = threadIdx.y;
#pragma unroll
    for (int j = 0; j < 32; j += 8)
        t[ty + j][tx] = W[(size_t)(by + ty + j) * CC + bx + tx];
    __syncthreads();
#pragma unroll
    for (int j = 0; j < 32; j += 8)
        WT[(size_t)(bx + ty + j) * CC + by + tx] = __float2half(t[tx][ty + j]);
}

// ---------------------------------------------------------------------------
// FP16 GEMM: D[M,N] = A[M,K] @ Bt[N,K]^T  (both k-contiguous, half)
// Block 128x128, BK=32, 128 threads (4 warps, warp tile 64x64),
// 4-stage cp.async pipeline, pitch-20-word conflict-free smem, occ 2.
// ---------------------------------------------------------------------------
#define BM 128
#define BN 128
#define BK 32
#define PITCHW 20                    // 32-bit words per row (32 halves + 8 pad)
#define AST_W (BM * PITCHW)          // 2560 words per A tile
#define STAGE_B (2 * AST_W * 4)      // 20480 bytes (A + B)
#define NSTAGE 4
#define SMEM_BYTES (NSTAGE * STAGE_B)   // 81920
#define NKT (CC / BK)                // 64

__device__ __forceinline__ void mma_f16(float* d, const unsigned* a, const unsigned* b) {
    asm volatile(
        "mma.sync.aligned.m16n8k16.row.col.f32.f16.f16.f32 "
        "{%0,%1,%2,%3}, {%4,%5,%6,%7}, {%8,%9}, {%0,%1,%2,%3};\n"
        : "+f"(d[0]), "+f"(d[1]), "+f"(d[2]), "+f"(d[3])
        : "r"(a[0]), "r"(a[1]), "r"(a[2]), "r"(a[3]), "r"(b[0]), "r"(b[1]));
}

__device__ __forceinline__ void cp16(uint32_t saddr, const void* gaddr) {
    asm volatile("cp.async.cg.shared.global [%0], [%1], 16;\n"
                 :: "r"(saddr), "l"(gaddr));
}

__device__ __forceinline__ void gemm_body(
    const __half* __restrict__ A, const __half* __restrict__ Bt,
    float* __restrict__ D, char* smem)
{
    const uint32_t sbase = smem_u32(smem);
    const int tid = threadIdx.x;
    const int wid = tid >> 5;
    const int lane = tid & 31;
    const int gp = lane >> 2;        // 0..7
    const int tg = lane & 3;         // 0..3
    const int wm = (wid & 1) << 6;   // 0, 64
    const int wn = (wid >> 1) << 6;  // 0, 64

    const int bm = blockIdx.y * BM;
    const int bn = blockIdx.x * BN;

    // loader mapping: row lr (+32j), 16B chunk lc (8 halves)
    const int lr = tid >> 2;         // 0..31
    const int lc = tid & 3;          // 0..3
    const __half* ga = A  + (size_t)(bm + lr) * CC + lc * 8;
    const __half* gb = Bt + (size_t)(bn + lr) * CC + lc * 8;
    const uint32_t swa = (uint32_t)(lr * PITCHW * 4 + lc * 16);

    float acc[4][8][4];
#pragma unroll
    for (int i = 0; i < 4; i++)
#pragma unroll
        for (int j = 0; j < 8; j++)
#pragma unroll
            for (int e = 0; e < 4; e++) acc[i][j][e] = 0.f;

#define LOAD_STAGE(ST, KT)                                                     \
    do {                                                                       \
        uint32_t _sa = sbase + (ST) * STAGE_B + swa;                           \
        uint32_t _sb = _sa + AST_W * 4;                                        \
        const __half* _ga = ga + (KT) * BK;                                    \
        const __half* _gb = gb + (KT) * BK;                                    \
        cp16(_sa,                    _ga);                                     \
        cp16(_sa + 32 * PITCHW * 4,  _ga + (size_t)32 * CC);                   \
        cp16(_sa + 64 * PITCHW * 4,  _ga + (size_t)64 * CC);                   \
        cp16(_sa + 96 * PITCHW * 4,  _ga + (size_t)96 * CC);                   \
        cp16(_sb,                    _gb);                                     \
        cp16(_sb + 32 * PITCHW * 4,  _gb + (size_t)32 * CC);                   \
        cp16(_sb + 64 * PITCHW * 4,  _gb + (size_t)64 * CC);                   \
        cp16(_sb + 96 * PITCHW * 4,  _gb + (size_t)96 * CC);                   \
        asm volatile("cp.async.commit_group;\n" ::: "memory");                 \
    } while (0)

    LOAD_STAGE(0, 0);
    LOAD_STAGE(1, 1);
    LOAD_STAGE(2, 2);

    const int abase0 = (wm + gp) * PITCHW + tg;
    const int bbase0 = (wn + gp) * PITCHW + tg;

    for (int kt = 0; kt < NKT; kt++) {
        int ahead = NKT - 1 - kt;
        if (ahead >= 2)      asm volatile("cp.async.wait_group 2;\n" ::: "memory");
        else if (ahead == 1) asm volatile("cp.async.wait_group 1;\n" ::: "memory");
        else                 asm volatile("cp.async.wait_group 0;\n" ::: "memory");
        __syncthreads();

        if (kt + 3 < NKT) LOAD_STAGE((kt + 3) & 3, kt + 3);

        const unsigned* As = (const unsigned*)(smem + (kt & 3) * STAGE_B);
        const unsigned* Bs = As + AST_W;

#pragma unroll
        for (int ks = 0; ks < 2; ks++) {       // two k16 steps (word offset 8)
            const int ko = ks * 8;
            unsigned af[4][4];
            unsigned bf[8][2];
#pragma unroll
            for (int mi = 0; mi < 4; mi++) {
                int b = abase0 + mi * 16 * PITCHW + ko;
                af[mi][0] = As[b];                    // (m=gp,    k=2tg)
                af[mi][1] = As[b + 8 * PITCHW];       // (m=gp+8,  k=2tg)
                af[mi][2] = As[b + 4];                // (m=gp,    k=2tg+8)
                af[mi][3] = As[b + 8 * PITCHW + 4];   // (m=gp+8,  k=2tg+8)
            }
#pragma unroll
            for (int ni = 0; ni < 8; ni++) {
                int b = bbase0 + ni * 8 * PITCHW + ko;
                bf[ni][0] = Bs[b];                    // (n=gp, k=2tg)
                bf[ni][1] = Bs[b + 4];                // (n=gp, k=2tg+8)
            }
#pragma unroll
            for (int mi = 0; mi < 4; mi++)
#pragma unroll
                for (int ni = 0; ni < 8; ni++)
                    mma_f16(acc[mi][ni], af[mi], bf[ni]);
        }
    }

    // epilogue (fp32 out)
#pragma unroll
    for (int mi = 0; mi < 4; mi++) {
        int r0 = bm + wm + mi * 16 + gp;
#pragma unroll
        for (int ni = 0; ni < 8; ni++) {
            int c0 = bn + wn + ni * 8 + tg * 2;
            *(float2*)&D[(size_t)r0 * CC + c0]       = make_float2(acc[mi][ni][0], acc[mi][ni][1]);
            *(float2*)&D[(size_t)(r0 + 8) * CC + c0] = make_float2(acc[mi][ni][2], acc[mi][ni][3]);
        }
    }
#undef LOAD_STAGE
}

// Fused k/v/r GEMMs: blockIdx.z selects operand triple (wave packing)
__global__ __launch_bounds__(128, 2) void gemm_fused3()
{
    extern __shared__ char smem[];
    const __half* A;
    const __half* B;
    float* D;
    if (blockIdx.z == 0)      { A = g_xk; B = g_WkT; D = g_k; }
    else if (blockIdx.z == 1) { A = g_xv; B = g_WvT; D = g_v; }
    else                      { A = g_xr; B = g_WrT; D = g_r; }
    gemm_body(A, B, D, smem);
}

__global__ __launch_bounds__(128, 2) void gemm_single(
    const __half* __restrict__ A, const __half* __restrict__ Bt, float* __restrict__ D)
{
    extern __shared__ char smem[];
    gemm_body(A, Bt, D, smem);
}

// ---------------------------------------------------------------------------
// WKV chunk-parallel scan (unchanged numerics, 128 chunks)
// ---------------------------------------------------------------------------
__global__ __launch_bounds__(256) void wkv_phaseA(const float* __restrict__ time_decay)
{
    int c = blockIdx.x * 256 + threadIdx.x;
    int ch = blockIdx.y;
    float w = -__expf(time_decay[c]);
    float p = 0.f, q = 0.f, o = -CUDART_INF_F;
    size_t idx = (size_t)(ch * CHUNK) * CC + c;
#pragma unroll 4
    for (int i = 0; i < CHUNK; i++, idx += CC) {
        float kt = g_k[idx];
        float vt = g_v[idx];
        float no = fmaxf(w + o, kt);
        float A2 = __expf(w + o - no);
        float B2 = __expf(kt - no);
        p = A2 * p + B2 * vt;
        q = A2 * q + B2;
        o = no;
    }
    g_lp[ch * CC + c] = p;
    g_lq[ch * CC + c] = q;
    g_lo[ch * CC + c] = o;
}

__global__ __launch_bounds__(256) void wkv_phaseB(const float* __restrict__ time_decay)
{
    int c = blockIdx.x * 256 + threadIdx.x;
    float w = -__expf(time_decay[c]);
    float d = w * (float)CHUNK;
    float p = 0.f, q = 0.f, o = -CUDART_INF_F;
    for (int ch = 0; ch < NCHUNK; ch++) {
        g_cp[ch * CC + c] = p;
        g_cq[ch * CC + c] = q;
        g_co[ch * CC + c] = o;
        float lp = g_lp[ch * CC + c];
        float lq = g_lq[ch * CC + c];
        float lo = g_lo[ch * CC + c];
        float o1 = o + d;
        float no = fmaxf(o1, lo);
        float e1 = __expf(o1 - no);
        float e2 = __expf(lo - no);
        p = e1 * p + e2 * lp;
        q = e1 * q + e2 * lq;
        o = no;
    }
}

// fuses sigmoid(r) gate; fp16 output (Wo GEMM A operand)
__global__ __launch_bounds__(256) void wkv_phaseC(
    const float* __restrict__ time_decay, const float* __restrict__ time_first)
{
    int c = blockIdx.x * 256 + threadIdx.x;
    int ch = blockIdx.y;
    float w = -__expf(time_decay[c]);
    float u = time_first[c];
    float p = g_cp[ch * CC + c];
    float q = g_cq[ch * CC + c];
    float o = g_co[ch * CC + c];
    size_t idx = (size_t)(ch * CHUNK) * CC + c;
#pragma unroll 4
    for (int i = 0; i < CHUNK; i++, idx += CC) {
        float kt = g_k[idx];
        float vt = g_v[idx];
        float rt = g_r[idx];
        float uk = u + kt;
        float no = fmaxf(o, uk);
        float Ae = __expf(o - no);
        float Be = __expf(uk - no);
        float y = __fdividef(Ae * p + Be * vt, Ae * q + Be);
        float sr = __fdividef(1.f, 1.f + __expf(-rt));
        g_y[idx] = __float2half(sr * y);
        float no2 = fmaxf(w + o, kt);
        float A2 = __expf(w + o - no2);
        float B2 = __expf(kt - no2);
        p = A2 * p + B2 * vt;
        q = A2 * q + B2;
        o = no2;
    }
}

// ---------------------------------------------------------------------------
// Launch
// ---------------------------------------------------------------------------
extern "C" void kernel_launch(void* const* d_in, const int* in_sizes, int n_in,
                              void* d_out, int out_size)
{
    (void)in_sizes; (void)n_in; (void)out_size;
    const float* x   = (const float*)d_in[0];
    const float* tfi = (const float*)d_in[1];
    const float* tmk = (const float*)d_in[2];
    const float* tmv = (const float*)d_in[3];
    const float* tmr = (const float*)d_in[4];
    const float* td  = (const float*)d_in[5];
    const float* Wk  = (const float*)d_in[6];
    const float* Wv  = (const float*)d_in[7];
    const float* Wr  = (const float*)d_in[8];
    const float* Wo  = (const float*)d_in[9];
    float* out = (float*)d_out;

    __half *p_y, *p_WoT;
    cudaGetSymbolAddress((void**)&p_y,  g_y);
    cudaGetSymbolAddress((void**)&p_WoT, g_WoT);

    cudaFuncSetAttribute(gemm_fused3, cudaFuncAttributeMaxDynamicSharedMemorySize, SMEM_BYTES);
    cudaFuncSetAttribute(gemm_single, cudaFuncAttributeMaxDynamicSharedMemorySize, SMEM_BYTES);

    const int elem4_blocks = (TT * CC / 4) / 256;  // 8192
    dim3 tgrid(CC / 32, CC / 32, 4), tblk(32, 8);
    transpose_half4<<<tgrid, tblk>>>(Wk, Wv, Wr, Wo);

    mix_kernel<<<elem4_blocks, 256>>>(x, tmk, tmv, tmr);

    dim3 g3(CC / BN, TT / BM, 3);   // (16, 32, 3) = 1536 CTAs
    gemm_fused3<<<g3, 128, SMEM_BYTES>>>();

    wkv_phaseA<<<dim3(CC / 256, NCHUNK), 256>>>(td);
    wkv_phaseB<<<CC / 256, 256>>>(td);
    wkv_phaseC<<<dim3(CC / 256, NCHUNK), 256>>>(td, tfi);

    dim3 g1(CC / BN, TT / BM);      // (16, 32) = 512 CTAs
    gemm_single<<<g1, 128, SMEM_BYTES>>>(p_y, p_WoT, out);
}